// round 6
// baseline (speedup 1.0000x reference)
#include <cuda_runtime.h>
#include <math.h>

#define DIMS 20
#define MULT 8
#define KCOMP 168
#define NPAIR (DIMS/2)
#define FROWF 44             // fast row floats: (g,g)x20 | (c,c) | pad2  (176B, 16B-aligned)
#define GROW 48              // general row: a[20] | b[20] | c | pad
#define LOG_NORM (-18.378770664093453f)
#define LN2F 0.6931471805599453f
#define EPS_VAR 1.0f
#define BASE_COV 0.1f
#define LOG2E 1.4426950408889634f

typedef unsigned long long u64;

__device__ __forceinline__ u64 pack2f(float lo, float hi) {
    u64 r; asm("mov.b64 %0, {%1, %2};" : "=l"(r) : "f"(lo), "f"(hi)); return r;
}
__device__ __forceinline__ void unpack2f(u64 v, float& lo, float& hi) {
    asm("mov.b64 {%0, %1}, %2;" : "=f"(lo), "=f"(hi) : "l"(v));
}
__device__ __forceinline__ u64 ffma2(u64 a, u64 b, u64 c) {
    u64 d; asm("fma.rn.f32x2 %0, %1, %2, %3;" : "=l"(d) : "l"(a), "l"(b), "l"(c)); return d;
}
__device__ __forceinline__ u64 fmul2(u64 a, u64 b) {
    u64 d; asm("mul.rn.f32x2 %0, %1, %2;" : "=l"(d) : "l"(a), "l"(b)); return d;
}
__device__ __forceinline__ u64 fadd2(u64 a, u64 b) {
    u64 d; asm("add.rn.f32x2 %0, %1, %2;" : "=l"(d) : "l"(a), "l"(b)); return d;
}
__device__ __forceinline__ float ex2f(float x) {
    float r; asm("ex2.approx.ftz.f32 %0, %1;" : "=f"(r) : "f"(x)); return r;
}

// ---------------------------------------------------------------------------
// Fused kernel, 128 threads/block, 512 samples/block (SPT=4 as 2 f32x2 pairs).
// Per-block prep (redundant, ~1-2us effective): softmax + fold constants.
// Fast path (uniform inv, true for bench inputs):
//   lanes of every f32x2 = (sample0, sample1)
//   t[n,k] = A_n + c_k + sum_d g_k[d]*x_d  -> 20 FFMA2 + 1 FADD2 per k per pair
// ---------------------------------------------------------------------------
__global__ void __launch_bounds__(128, 4)
gm_fused_kernel(const float* __restrict__ sample,
                const float* __restrict__ alpha,
                const float* __restrict__ mu,
                const float* __restrict__ cov,
                float* __restrict__ out, int n_total) {
    __shared__ float sB[KCOMP * GROW];   // 32256B; fast path uses 168*44+40 = 7432 floats
    __shared__ float red[128];
    __shared__ int sflag;

    const int t = threadIdx.x;
    if (t == 0) sflag = 1;

    // ---- softmax over alpha (168 values, 128 threads)
    float a0v = alpha[t];
    float a1v = (t + 128 < KCOMP) ? alpha[t + 128] : -1e30f;
    red[t] = fmaxf(a0v, a1v); __syncthreads();
    for (int s = 64; s > 0; s >>= 1) { if (t < s) red[t] = fmaxf(red[t], red[t + s]); __syncthreads(); }
    const float mx = red[0]; __syncthreads();
    float ev = expf(a0v - mx) + ((t + 128 < KCOMP) ? expf(a1v - mx) : 0.f);
    red[t] = ev; __syncthreads();
    for (int s = 64; s > 0; s >>= 1) { if (t < s) red[t] += red[t + s]; __syncthreads(); }
    const float wsum = red[0];
    __syncthreads();

    // ---- uniformity check: inv[k][d] == inv[0][d] for all k,d
    {
        int ok = 1;
        for (int k = t; k < KCOMP; k += 128) {
            const int i = k / MULT;
            #pragma unroll
            for (int d = 0; d < DIMS; d++) {
                float sc = (d < i) ? EPS_VAR : 1.0f;
                float inv  = 1.0f / (cov[k * DIMS + d] * sc);
                float inv0 = 1.0f / cov[d];
                ok &= (inv == inv0);
            }
        }
        if (!ok) atomicAnd(&sflag, 0);
    }
    __syncthreads();
    const int flag = sflag;

    // ---- build shared tables
    if (flag) {
        for (int k = t; k < KCOMP; k += 128) {
            const int i = k / MULT;
            float sum_mu2inv = 0.f;
            #pragma unroll
            for (int d = 0; d < DIMS; d++) {
                float inv = 1.0f / cov[d];           // uniform
                float mm = mu[k * DIMS + d];
                float g = LOG2E * inv * mm;
                sB[k * FROWF + 2 * d]     = g;
                sB[k * FROWF + 2 * d + 1] = g;
                sum_mu2inv += mm * mm * inv;
            }
            float log2det = (float)i * log2f(EPS_VAR) + (float)(DIMS - i) * log2f(BASE_COV);
            float w = expf(alpha[k] - mx) / wsum;
            float c = log2f(w) - 0.5f * log2det - 0.5f * LOG2E * sum_mu2inv;
            sB[k * FROWF + 40] = c;
            sB[k * FROWF + 41] = c;
            sB[k * FROWF + 42] = 0.f;
            sB[k * FROWF + 43] = 0.f;
        }
        // duplicated a-row at offset KCOMP*FROWF
        if (t < DIMS) {
            float a = -0.5f * LOG2E * (1.0f / cov[t]);
            sB[KCOMP * FROWF + 2 * t]     = a;
            sB[KCOMP * FROWF + 2 * t + 1] = a;
        }
    } else {
        for (int k = t; k < KCOMP; k += 128) {
            const int i = k / MULT;
            float sum_mu2inv = 0.f;
            #pragma unroll
            for (int d = 0; d < DIMS; d++) {
                float sc = (d < i) ? EPS_VAR : 1.0f;
                float inv = 1.0f / (cov[k * DIMS + d] * sc);
                float mm = mu[k * DIMS + d];
                sB[k * GROW + d]        = -0.5f * LOG2E * inv;
                sB[k * GROW + DIMS + d] =  LOG2E * inv * mm;
                sum_mu2inv += mm * mm * inv;
            }
            float log2det = (float)i * log2f(EPS_VAR) + (float)(DIMS - i) * log2f(BASE_COV);
            float w = expf(alpha[k] - mx) / wsum;
            sB[k * GROW + 2 * DIMS] = log2f(w) - 0.5f * log2det - 0.5f * LOG2E * sum_mu2inv
                                    + LOG2E * LOG_NORM;
            #pragma unroll
            for (int f = 2 * DIMS + 1; f < GROW; f++) sB[k * GROW + f] = 0.f;
        }
    }
    __syncthreads();

    // ---- sample indices: 4 per thread, lanes pair (s0,s1) and (s2,s3)
    const int base = blockIdx.x * 512;
    const int n0 = base + t, n1 = base + 128 + t, n2 = base + 256 + t, n3 = base + 384 + t;
    const bool v0 = n0 < n_total, v1 = n1 < n_total, v2 = n2 < n_total, v3 = n3 < n_total;
    const size_t i0 = v0 ? (size_t)n0 : 0, i1 = v1 ? (size_t)n1 : 0;
    const size_t i2 = v2 ? (size_t)n2 : 0, i3 = v3 ? (size_t)n3 : 0;

    if (flag) {
        // ---- load + transpose x into sample-pair lanes
        u64 xa[DIMS], xb[DIMS];          // xa[d]=(x_{s0,d},x_{s1,d}), xb: (s2,s3)
        {
            const float4* p0 = (const float4*)(sample + i0 * DIMS);
            const float4* p1 = (const float4*)(sample + i1 * DIMS);
            const float4* p2 = (const float4*)(sample + i2 * DIMS);
            const float4* p3 = (const float4*)(sample + i3 * DIMS);
            #pragma unroll
            for (int j = 0; j < 5; j++) {
                float4 q0 = p0[j], q1 = p1[j], q2 = p2[j], q3 = p3[j];
                xa[4*j+0] = pack2f(q0.x, q1.x); xb[4*j+0] = pack2f(q2.x, q3.x);
                xa[4*j+1] = pack2f(q0.y, q1.y); xb[4*j+1] = pack2f(q2.y, q3.y);
                xa[4*j+2] = pack2f(q0.z, q1.z); xb[4*j+2] = pack2f(q2.z, q3.z);
                xa[4*j+3] = pack2f(q0.w, q1.w); xb[4*j+3] = pack2f(q2.w, q3.w);
            }
        }

        // ---- A-term per pair: A2 = sum_d a_d * x_d^2 (both lanes independently)
        u64 Aa, Ab;
        {
            const u64* ap = (const u64*)(sB + KCOMP * FROWF);
            u64 ta = fmul2(fmul2(xa[0], xa[0]), ap[0]);
            u64 tb = fmul2(fmul2(xb[0], xb[0]), ap[0]);
            #pragma unroll
            for (int d = 1; d < DIMS; d++) {
                ta = ffma2(fmul2(xa[d], xa[d]), ap[d], ta);
                tb = ffma2(fmul2(xb[d], xb[d]), ap[d], tb);
            }
            Aa = ta; Ab = tb;
        }

        u64 densa = pack2f(0.f, 0.f), densb = densa;

        #pragma unroll 1
        for (int k = 0; k < KCOMP; k++) {
            const u64* R = (const u64*)(sB + k * FROWF);   // (g,g)[0..19], (c,c)[20]
            const u64 cc = R[20];
            u64 acca = ffma2(xa[0], R[0], cc);
            u64 accb = ffma2(xb[0], R[0], cc);
            #pragma unroll
            for (int d = 1; d < DIMS; d++) {
                acca = ffma2(xa[d], R[d], acca);
                accb = ffma2(xb[d], R[d], accb);
            }
            float la, ha, lb, hb;
            unpack2f(acca, la, ha);
            unpack2f(accb, lb, hb);
            densa = fadd2(densa, pack2f(ex2f(la), ex2f(ha)));
            densb = fadd2(densb, pack2f(ex2f(lb), ex2f(hb)));
        }

        float d0, d1, d2, d3, A0, A1, A2v, A3;
        unpack2f(densa, d0, d1); unpack2f(densb, d2, d3);
        unpack2f(Aa, A0, A1);    unpack2f(Ab, A2v, A3);
        if (v0) out[n0] = fmaf(A0,  LN2F, logf(d0)) + LOG_NORM;
        if (v1) out[n1] = fmaf(A1,  LN2F, logf(d1)) + LOG_NORM;
        if (v2) out[n2] = fmaf(A2v, LN2F, logf(d2)) + LOG_NORM;
        if (v3) out[n3] = fmaf(A3,  LN2F, logf(d3)) + LOG_NORM;
    } else {
        // ---- general path: full Horner quadratic, (even,odd)-dim packing,
        //      two samples at a time, two passes. Correct but slower; never
        //      taken for the bench inputs.
        #pragma unroll 1
        for (int pass = 0; pass < 2; pass++) {
            const size_t ia = pass ? i2 : i0;
            const size_t ib = pass ? i3 : i1;
            u64 x0[NPAIR], x1[NPAIR];
            const ulonglong2* p0 = (const ulonglong2*)(sample + ia * DIMS);
            const ulonglong2* p1 = (const ulonglong2*)(sample + ib * DIMS);
            #pragma unroll
            for (int j = 0; j < 5; j++) {
                ulonglong2 q0 = p0[j], q1 = p1[j];
                x0[2*j] = q0.x; x0[2*j+1] = q0.y;
                x1[2*j] = q1.x; x1[2*j+1] = q1.y;
            }
            float dens0 = 0.f, dens1 = 0.f;
            for (int k = 0; k < KCOMP; k++) {
                const u64* R = (const u64*)(sB + k * GROW);
                const u64 c2 = R[20];
                u64 acc0 = c2, acc1 = c2;
                #pragma unroll
                for (int j = 0; j < NPAIR; j++) {
                    u64 t0 = ffma2(x0[j], R[j], R[10 + j]);
                    acc0 = ffma2(x0[j], t0, acc0);
                    u64 t1 = ffma2(x1[j], R[j], R[10 + j]);
                    acc1 = ffma2(x1[j], t1, acc1);
                }
                float l, h;
                unpack2f(acc0, l, h); dens0 += ex2f(l + h);
                unpack2f(acc1, l, h); dens1 += ex2f(l + h);
            }
            const int na = pass ? n2 : n0, nb = pass ? n3 : n1;
            if (na < n_total) out[na] = logf(dens0);
            if (nb < n_total) out[nb] = logf(dens1);
        }
    }
}

extern "C" void kernel_launch(void* const* d_in, const int* in_sizes, int n_in,
                              void* d_out, int out_size) {
    const float* sample = (const float*)d_in[0];
    const float* alpha  = (const float*)d_in[1];
    const float* mu     = (const float*)d_in[2];
    const float* cov    = (const float*)d_in[3];
    float* out = (float*)d_out;

    const int n_total = in_sizes[0] / DIMS;
    const int blocks = (n_total + 511) / 512;    // 1024 for N=524288

    gm_fused_kernel<<<blocks, 128>>>(sample, alpha, mu, cov, out, n_total);
}